// round 15
// baseline (speedup 1.0000x reference)
#include <cuda_runtime.h>
#include <cuda_fp16.h>
#include <math.h>
#include <stdint.h>

#define BATCH 8
#define NINST 8192
#define DIM   512
#define HID   64
#define TOPK_K 2457

#define GCHUNKS 64
#define GROWS   (NINST / GCHUNKS)   // 128

#define KCHUNKS 16
#define KLEN    (DIM / KCHUNKS)     // 32

// attn tiling
#define BM 128
#define BN 64
#define BK 32
#define NCH (DIM / BK)              // 16

#define CAP  512
#define BAND 1e-3f

// scratch (device globals; no allocation allowed)
__device__ __align__(16) __half g_w1h[DIM * HID];  // aW1 fp16, [k][n]
__device__ float    g_part[GCHUNKS * BATCH * DIM];
__device__ float    g_p1[KCHUNKS * BATCH * DIM];
__device__ float    g_p2[KCHUNKS * BATCH * DIM];
__device__ unsigned g_thr[BATCH];                 // approx kth weight (bits)
__device__ int      g_above[BATCH];               // #(w > thr+BAND)
__device__ int      g_ccnt[BATCH];                // candidate count
__device__ int      g_cand[BATCH][CAP];           // candidate indices
__device__ float    g_cval[BATCH][CAP];           // refined fp32 weights
__device__ unsigned char g_flag[BATCH * NINST];   // boundary-selected flags

__device__ __forceinline__ float gelu_f(float v) {
    float u = 0.7978845608028654f * (v + 0.044715f * v * v * v);
    return 0.5f * v * (1.0f + tanhf(u));
}

__device__ __forceinline__ void cp16(uint32_t sdst, const void* gsrc) {
    asm volatile("cp.async.cg.shared.global [%0], [%1], 16;" :: "r"(sdst), "l"(gsrc));
}

__device__ __forceinline__ void hmma(float* c, const unsigned* a, const unsigned* b) {
    asm volatile(
        "mma.sync.aligned.m16n8k16.row.col.f32.f16.f16.f32 "
        "{%0,%1,%2,%3}, {%4,%5,%6,%7}, {%8,%9}, {%0,%1,%2,%3};"
        : "+f"(c[0]), "+f"(c[1]), "+f"(c[2]), "+f"(c[3])
        : "r"(a[0]), "r"(a[1]), "r"(a[2]), "r"(a[3]), "r"(b[0]), "r"(b[1]));
}

__device__ __forceinline__ void ldm_x4(unsigned* r, uint32_t addr) {
    asm volatile("ldmatrix.sync.aligned.m8n8.x4.shared.b16 {%0,%1,%2,%3}, [%4];"
                 : "=r"(r[0]), "=r"(r[1]), "=r"(r[2]), "=r"(r[3]) : "r"(addr));
}
__device__ __forceinline__ void ldm_x4t(unsigned* r, uint32_t addr) {
    asm volatile("ldmatrix.sync.aligned.m8n8.x4.trans.shared.b16 {%0,%1,%2,%3}, [%4];"
                 : "=r"(r[0]), "=r"(r[1]), "=r"(r[2]), "=r"(r[3]) : "r"(addr));
}

// ---------------------------------------------------------------------------
// Kernel 0: round aW1 to fp16.
// ---------------------------------------------------------------------------
__global__ __launch_bounds__(256) void conv_w1_kernel(const float* __restrict__ aW1)
{
    int i = blockIdx.x * 256 + threadIdx.x;
    if (i < DIM * HID)
        g_w1h[i] = __float2half_rn(aW1[i]);
}

// ---------------------------------------------------------------------------
// Kernel 1: fused attention-score MLP, plain fp16 HMMA, A+B double-buffered,
// ONE barrier per K-chunk (R13 ordering, measured 105.5 us total):
//   store A -> wait_group 0 -> barrier -> issue loadB(c+1) -> ldmatrix/MMA.
// x prefetch in NAMED registers (xr/xn) — no runtime-indexed arrays (R14
// lesson: those spill to local memory).
// ---------------------------------------------------------------------------
__global__ __launch_bounds__(256) void attn_kernel(
    const float* __restrict__ x,
    const float* __restrict__ ab1,
    const float* __restrict__ aW2,
    const float* __restrict__ ab2,
    float* __restrict__ wout)
{
    __shared__ __align__(16) __half Ah[2][BM][40];
    __shared__ __align__(16) __half Bh[2][BK][72];
    __shared__ float red[128][2];

    const int tid   = threadIdx.x;
    const int lane  = tid & 31;
    const int warp  = tid >> 5;
    const int warpM = warp >> 1;
    const int warpN = warp & 1;
    const long rowBase = (long)blockIdx.x * BM;
    const float* xb = x + rowBase * DIM;

    float acc[2][4][4];
    #pragma unroll
    for (int mi = 0; mi < 2; mi++)
        #pragma unroll
        for (int ni = 0; ni < 4; ni++)
            #pragma unroll
            for (int q = 0; q < 4; q++) acc[mi][ni][q] = 0.f;

    auto loadB = [&](int s, int c) {
        int r = tid >> 3, g = tid & 7;
        uint32_t dh = (uint32_t)__cvta_generic_to_shared(&Bh[s][r][g * 8]);
        cp16(dh, g_w1h + (c * BK + r) * HID + g * 8);
        asm volatile("cp.async.commit_group;");
    };

    const int ar = tid >> 1;
    const int ah = tid & 1;
    const float* xrow = xb + (long)ar * DIM + ah * 16;

    loadB(0, 0);   // prologue: B group for chunk 0 in flight
    float4 xr[4];
    #pragma unroll
    for (int q = 0; q < 4; q++)
        xr[q] = *reinterpret_cast<const float4*>(xrow + q * 4);

    for (int c = 0; c < NCH; c++) {
        const int st = c & 1;
        // convert 16 floats -> 8 packed half2
        unsigned hw[8];
        const float* xv = reinterpret_cast<const float*>(xr);
        #pragma unroll
        for (int e = 0; e < 8; e++) {
            __half2 hp = __float22half2_rn(make_float2(xv[2 * e], xv[2 * e + 1]));
            hw[e] = *reinterpret_cast<unsigned*>(&hp);
        }
        float4 xn[4];
        if (c + 1 < NCH) {
            #pragma unroll
            for (int q = 0; q < 4; q++)
                xn[q] = *reinterpret_cast<const float4*>(xrow + (c + 1) * BK + q * 4);
        }
        // store A stage st (safe: stage-st reads at c-2 precede barrier(c-1))
        {
            char* pa = reinterpret_cast<char*>(&Ah[st][0][0]) + ar * 80 + ah * 32;
            *reinterpret_cast<uint4*>(pa)      = make_uint4(hw[0], hw[1], hw[2], hw[3]);
            *reinterpret_cast<uint4*>(pa + 16) = make_uint4(hw[4], hw[5], hw[6], hw[7]);
        }
        // chunk c's B group (issued last iteration / prologue) completes here
        asm volatile("cp.async.wait_group 0;");
        __syncthreads();   // publishes A stores + B chunk c; orders prior reads
        // issue next B load AFTER the barrier (prior-stage reads are done)
        if (c + 1 < NCH)
            loadB((c + 1) & 1, c + 1);

        #pragma unroll
        for (int ks = 0; ks < 2; ks++) {
            const int k0 = ks * 16;
            unsigned Ahf[2][4];
            #pragma unroll
            for (int mi = 0; mi < 2; mi++) {
                int arow2 = warpM * 32 + mi * 16 + (lane & 15);
                int acol  = k0 + ((lane >> 4) << 3);
                uint32_t base = (uint32_t)__cvta_generic_to_shared(&Ah[st][arow2][acol]);
                ldm_x4(Ahf[mi], base);
            }
            unsigned Bhf[4][2];
            #pragma unroll
            for (int pr = 0; pr < 2; pr++) {
                int brow = k0 + (lane & 15);
                int bcol = warpN * 32 + pr * 16 + ((lane >> 4) << 3);
                unsigned t4[4];
                uint32_t bb = (uint32_t)__cvta_generic_to_shared(&Bh[st][brow][bcol]);
                ldm_x4t(t4, bb);
                Bhf[pr * 2][0] = t4[0]; Bhf[pr * 2][1] = t4[1];
                Bhf[pr * 2 + 1][0] = t4[2]; Bhf[pr * 2 + 1][1] = t4[3];
            }
            #pragma unroll
            for (int mi = 0; mi < 2; mi++)
                #pragma unroll
                for (int ni = 0; ni < 4; ni++)
                    hmma(acc[mi][ni], Ahf[mi], Bhf[ni]);
        }
        #pragma unroll
        for (int q = 0; q < 4; q++) xr[q] = xn[q];
    }

    const int lk = lane & 3;
    const int lr = lane >> 2;
    float b1v[4][2], w2v[4][2];
    #pragma unroll
    for (int ni = 0; ni < 4; ni++) {
        int col = warpN * 32 + ni * 8 + 2 * lk;
        b1v[ni][0] = ab1[col];     b1v[ni][1] = ab1[col + 1];
        w2v[ni][0] = aW2[col];     w2v[ni][1] = aW2[col + 1];
    }
    float p[2][2] = {{0.f, 0.f}, {0.f, 0.f}};
    #pragma unroll
    for (int mi = 0; mi < 2; mi++)
        #pragma unroll
        for (int ni = 0; ni < 4; ni++) {
            p[mi][0] += gelu_f(acc[mi][ni][0] + b1v[ni][0]) * w2v[ni][0]
                      + gelu_f(acc[mi][ni][1] + b1v[ni][1]) * w2v[ni][1];
            p[mi][1] += gelu_f(acc[mi][ni][2] + b1v[ni][0]) * w2v[ni][0]
                      + gelu_f(acc[mi][ni][3] + b1v[ni][1]) * w2v[ni][1];
        }
    #pragma unroll
    for (int mi = 0; mi < 2; mi++)
        #pragma unroll
        for (int h = 0; h < 2; h++) {
            p[mi][h] += __shfl_xor_sync(0xffffffffu, p[mi][h], 1);
            p[mi][h] += __shfl_xor_sync(0xffffffffu, p[mi][h], 2);
        }
    if (lk == 0) {
        #pragma unroll
        for (int mi = 0; mi < 2; mi++) {
            int r = warpM * 32 + mi * 16 + lr;
            red[r][warpN]     = p[mi][0];
            red[r + 8][warpN] = p[mi][1];
        }
    }
    __syncthreads();
    if (tid < 128) {
        float s = red[tid][0] + red[tid][1] + ab2[0];
        wout[rowBase + tid] = 1.0f / (1.0f + expf(-s));
    }
}

// ---------------------------------------------------------------------------
// Kernel 2: radix-select with parallel suffix-scan bucket pick.
// ---------------------------------------------------------------------------
__global__ __launch_bounds__(512) void select_kernel(const float* __restrict__ w)
{
    __shared__ unsigned sv[NINST];
    __shared__ int hist[16][256];
    __shared__ int scan[256];
    __shared__ unsigned s_prefix;
    __shared__ int s_k, s_above, s_cnt;

    const int b = blockIdx.x;
    const int tid = threadIdx.x;
    const int wid = tid >> 5;
    const float* wb = w + b * NINST;

    for (int i = tid; i < NINST; i += 512)
        sv[i] = __float_as_uint(wb[i]);
    if (tid == 0) { s_prefix = 0u; s_k = TOPK_K; s_above = 0; s_cnt = 0; }
    __syncthreads();

    for (int r = 0; r < 4; r++) {
        for (int i = tid; i < 16 * 256; i += 512)
            hist[i >> 8][i & 255] = 0;
        __syncthreads();
        const unsigned pref = s_prefix;
        const int k = s_k;
        const int sh = 24 - 8 * r;
        for (int i = tid; i < NINST; i += 512) {
            unsigned v = sv[i];
            bool ok = (r == 0) || ((v >> (sh + 8)) == pref);
            if (ok) atomicAdd(&hist[wid][(v >> sh) & 255], 1);
        }
        __syncthreads();
        if (tid < 256) {
            int s = hist[0][tid];
            #pragma unroll
            for (int h = 1; h < 16; h++) s += hist[h][tid];
            scan[tid] = s;
        }
        __syncthreads();
        // suffix sums (count of elements in buckets >= i)
        #pragma unroll
        for (int off = 1; off < 256; off <<= 1) {
            int add = 0;
            if (tid < 256 && tid + off < 256) add = scan[tid + off];
            __syncthreads();
            if (tid < 256) scan[tid] += add;
            __syncthreads();
        }
        if (tid < 256) {
            int cumi  = scan[tid];
            int cumnx = (tid == 255) ? 0 : scan[tid + 1];
            if (cumi >= k && cumnx < k) {
                s_prefix = (pref << 8) | (unsigned)tid;
                s_k = k - cumnx;
            }
        }
        __syncthreads();
    }

    const float t   = __uint_as_float(s_prefix);
    const float thi = t + BAND;
    const float tlo = t - BAND;

    int la = 0;
    for (int i = tid; i < NINST; i += 512) {
        float wv = __uint_as_float(sv[i]);
        g_flag[b * NINST + i] = 0;
        if (wv > thi) la++;
        else if (wv >= tlo) {
            int p = atomicAdd(&s_cnt, 1);
            if (p < CAP) g_cand[b][p] = i;
        }
    }
    atomicAdd(&s_above, la);
    __syncthreads();
    if (tid == 0) {
        g_thr[b]   = s_prefix;
        g_above[b] = s_above;
        g_ccnt[b]  = s_cnt < CAP ? s_cnt : CAP;
    }
}

// ---------------------------------------------------------------------------
// Kernel 3: exact fp32 score recompute for band candidates.
// grid (128, BATCH) — doubled candidate parallelism (refine was 10.2 us at
// occ 34% with 2-3 serial candidates per block).
// ---------------------------------------------------------------------------
__global__ __launch_bounds__(256) void refine_kernel(
    const float* __restrict__ x,  const float* __restrict__ aW1,
    const float* __restrict__ ab1, const float* __restrict__ aW2,
    const float* __restrict__ ab2)
{
    const int b = blockIdx.y;
    const int cnt = g_ccnt[b];
    __shared__ float sx[DIM];
    __shared__ float sh4[4][64];
    __shared__ float sr[2];
    const int tid = threadIdx.x;
    const int q = tid >> 6;       // K quarter
    const int j = tid & 63;       // hidden unit

    for (int ci = blockIdx.x; ci < cnt; ci += 128) {
        const int idx = g_cand[b][ci];
        const float* xr = x + ((long)b * NINST + idx) * DIM;
        sx[tid]       = xr[tid];
        sx[tid + 256] = xr[tid + 256];
        __syncthreads();

        const float* wp = aW1 + (long)(q * 128) * HID + j;
        const float* xq = sx + q * 128;
        float acc = 0.f;
        #pragma unroll
        for (int g0 = 0; g0 < 128; g0 += 16) {
            float wv[16];
            #pragma unroll
            for (int t = 0; t < 16; t++)
                wv[t] = wp[(long)(g0 + t) * HID];
            #pragma unroll
            for (int t = 0; t < 16; t++)
                acc += xq[g0 + t] * wv[t];
        }
        sh4[q][j] = acc;
        __syncthreads();

        if (tid < 64) {
            float hsum = sh4[0][j] + sh4[1][j] + sh4[2][j] + sh4[3][j];
            float hv = gelu_f(hsum + ab1[j]) * aW2[j];
            #pragma unroll
            for (int off = 16; off >= 1; off >>= 1)
                hv += __shfl_down_sync(0xffffffffu, hv, off);
            if ((j & 31) == 0) sr[j >> 5] = hv;
        }
        __syncthreads();
        if (tid == 0) {
            float logit = sr[0] + sr[1] + ab2[0];
            g_cval[b][ci] = 1.0f / (1.0f + expf(-logit));
        }
        __syncthreads();
    }
}

// ---------------------------------------------------------------------------
// Kernel 4: exact ranking among candidates -> flags (value desc, index asc).
// ---------------------------------------------------------------------------
__global__ __launch_bounds__(256) void finalize_kernel()
{
    __shared__ float v[CAP];
    __shared__ int  ix[CAP];
    const int b = blockIdx.x;
    const int tid = threadIdx.x;
    const int cnt  = g_ccnt[b];
    const int need = TOPK_K - g_above[b];

    for (int i = tid; i < cnt; i += 256) { v[i] = g_cval[b][i]; ix[i] = g_cand[b][i]; }
    __syncthreads();
    for (int i = tid; i < cnt; i += 256) {
        float vi = v[i]; int xi = ix[i];
        int rank = 0;
        for (int j = 0; j < cnt; j++)
            rank += (v[j] > vi) || (v[j] == vi && ix[j] < xi);
        if (rank < need) g_flag[b * NINST + xi] = 1;
    }
}

// ---------------------------------------------------------------------------
// Kernel 5: weighted gather-sum with per-block index compaction.
// ---------------------------------------------------------------------------
__global__ __launch_bounds__(128) void gather_kernel(
    const float* __restrict__ x, const float* __restrict__ w)
{
    __shared__ int   sel[GROWS];
    __shared__ float sw[GROWS];
    __shared__ int   wbase[4];
    __shared__ int   scount;

    const int b  = blockIdx.y;
    const int rc = blockIdx.x;
    const int r0 = rc * GROWS;
    const int tid = threadIdx.x;
    const int lane = tid & 31;
    const int wrp = tid >> 5;

    const float thi = __uint_as_float(g_thr[b]) + BAND;

    float wi = w[b * NINST + r0 + tid];
    bool pick = (wi > thi) || g_flag[b * NINST + r0 + tid];
    unsigned mask = __ballot_sync(0xffffffffu, pick);
    int wcnt = __popc(mask);
    if (lane == 0) wbase[wrp] = wcnt;
    __syncthreads();
    if (tid == 0) {
        int s = 0;
        #pragma unroll
        for (int q = 0; q < 4; q++) { int c = wbase[q]; wbase[q] = s; s += c; }
        scount = s;
    }
    __syncthreads();
    if (pick) {
        int pos = wbase[wrp] + __popc(mask & ((1u << lane) - 1u));
        sel[pos] = tid;
        sw[pos]  = wi;
    }
    __syncthreads();

    const int d4 = tid * 4;
    const int nsel = scount;
    const float* xb = x + ((long)b * NINST + r0) * DIM + d4;

    float4 acc = make_float4(0.f, 0.f, 0.f, 0.f);
    for (int s = 0; s < nsel; s++) {
        float ws = sw[s];
        float4 xv = *reinterpret_cast<const float4*>(xb + (long)sel[s] * DIM);
        acc.x += ws * xv.x; acc.y += ws * xv.y;
        acc.z += ws * xv.z; acc.w += ws * xv.w;
    }
    *reinterpret_cast<float4*>(&g_part[(rc * BATCH + b) * DIM + d4]) = acc;
}

// ---------------------------------------------------------------------------
// Kernel 6: mlp1 split-K partials with inline emb reduction.
// ---------------------------------------------------------------------------
__global__ __launch_bounds__(128) void mlp1_part_kernel(
    const float* __restrict__ W, float* __restrict__ part)
{
    __shared__ float s_in[BATCH][KLEN];
    const int kc = blockIdx.y;
    const int j  = blockIdx.x * 128 + threadIdx.x;

    #pragma unroll
    for (int it = 0; it < (BATCH * KLEN) / 128; it++) {
        int i = it * 128 + threadIdx.x;
        int bb = i / KLEN, dd = i % KLEN;
        const float* p = g_part + bb * DIM + kc * KLEN + dd;
        float s0 = 0.f, s1 = 0.f;
        #pragma unroll
        for (int rc = 0; rc < GCHUNKS; rc += 2) {
            s0 += p[(long)rc * BATCH * DIM];
            s1 += p[(long)(rc + 1) * BATCH * DIM];
        }
        s_in[bb][dd] = (s0 + s1) * (1.0f / (float)TOPK_K);
    }
    __syncthreads();

    float acc[BATCH];
    #pragma unroll
    for (int bb = 0; bb < BATCH; bb++) acc[bb] = 0.f;

    #pragma unroll 4
    for (int dd = 0; dd < KLEN; dd++) {
        float wv = W[(long)(kc * KLEN + dd) * DIM + j];
        #pragma unroll
        for (int bb = 0; bb < BATCH; bb++)
            acc[bb] += s_in[bb][dd] * wv;
    }
    #pragma unroll
    for (int bb = 0; bb < BATCH; bb++)
        part[(kc * BATCH + bb) * DIM + j] = acc[bb];
}

// ---------------------------------------------------------------------------
// Kernel 7: mlp2 split-K partials with inline (reduce p1 + bias + gelu).
// ---------------------------------------------------------------------------
__global__ __launch_bounds__(128) void mlp2_part_kernel(
    const float* __restrict__ W, const float* __restrict__ b1,
    float* __restrict__ part)
{
    __shared__ float s_in[BATCH][KLEN];
    const int kc = blockIdx.y;
    const int j  = blockIdx.x * 128 + threadIdx.x;

    #pragma unroll
    for (int it = 0; it < (BATCH * KLEN) / 128; it++) {
        int i = it * 128 + threadIdx.x;
        int bb = i / KLEN, dd = i % KLEN;
        const float* p = g_p1 + bb * DIM + kc * KLEN + dd;
        float s = 0.f;
        #pragma unroll
        for (int c = 0; c < KCHUNKS; c++)
            s += p[(long)c * BATCH * DIM];
        s_in[bb][dd] = gelu_f(s + b1[kc * KLEN + dd]);
    }
    __syncthreads();

    float acc[BATCH];
    #pragma unroll
    for (int bb = 0; bb < BATCH; bb++) acc[bb] = 0.f;

    #pragma unroll 4
    for (int dd = 0; dd < KLEN; dd++) {
        float wv = W[(long)(kc * KLEN + dd) * DIM + j];
        #pragma unroll
        for (int bb = 0; bb < BATCH; bb++)
            acc[bb] += s_in[bb][dd] * wv;
    }
    #pragma unroll
    for (int bb = 0; bb < BATCH; bb++)
        part[(kc * BATCH + bb) * DIM + j] = acc[bb];
}

// ---------------------------------------------------------------------------
// Kernel 8: reduce mlp2 partials + bias -> out.
// ---------------------------------------------------------------------------
__global__ __launch_bounds__(512) void mlp2_reduce_kernel(
    const float* __restrict__ bias, float* __restrict__ out)
{
    const int b = blockIdx.x;
    const int j = threadIdx.x;
    float s = 0.f;
    #pragma unroll
    for (int kc = 0; kc < KCHUNKS; kc++)
        s += g_p2[(kc * BATCH + b) * DIM + j];
    out[b * DIM + j] = s + bias[j];
}

// ---------------------------------------------------------------------------
extern "C" void kernel_launch(void* const* d_in, const int* in_sizes, int n_in,
                              void* d_out, int out_size)
{
    const float* x   = (const float*)d_in[0];
    const float* aW1 = (const float*)d_in[1];
    const float* ab1 = (const float*)d_in[2];
    const float* aW2 = (const float*)d_in[3];
    const float* ab2 = (const float*)d_in[4];
    const float* pW1 = (const float*)d_in[5];
    const float* pb1 = (const float*)d_in[6];
    const float* pW2 = (const float*)d_in[7];
    const float* pb2 = (const float*)d_in[8];

    float* out = (float*)d_out;
    float* proj    = out;                 // [B, DIM]
    float* weights = out + BATCH * DIM;   // [B, NINST]

    float* d_p1;  cudaGetSymbolAddress((void**)&d_p1, g_p1);
    float* d_p2;  cudaGetSymbolAddress((void**)&d_p2, g_p2);

    conv_w1_kernel<<<(DIM * HID + 255) / 256, 256>>>(aW1);
    attn_kernel<<<(BATCH * NINST) / BM, 256>>>(x, ab1, aW2, ab2, weights);
    select_kernel<<<BATCH, 512>>>(weights);
    refine_kernel<<<dim3(128, BATCH), 256>>>(x, aW1, ab1, aW2, ab2);
    finalize_kernel<<<BATCH, 256>>>();
    gather_kernel<<<dim3(GCHUNKS, BATCH), 128>>>(x, weights);
    mlp1_part_kernel<<<dim3(DIM / 128, KCHUNKS), 128>>>(pW1, d_p1);
    mlp2_part_kernel<<<dim3(DIM / 128, KCHUNKS), 128>>>(pW2, pb1, d_p2);
    mlp2_reduce_kernel<<<BATCH, 512>>>(pb2, proj);
}

// round 16
// speedup vs baseline: 1.0462x; 1.0462x over previous
#include <cuda_runtime.h>
#include <cuda_fp16.h>
#include <math.h>
#include <stdint.h>

#define BATCH 8
#define NINST 8192
#define DIM   512
#define HID   64
#define TOPK_K 2457

#define GCHUNKS 64
#define GROWS   (NINST / GCHUNKS)   // 128

#define KCHUNKS 16
#define KLEN    (DIM / KCHUNKS)     // 32

// attn tiling
#define BM 128
#define BN 64
#define BK 32
#define NCH (DIM / BK)              // 16

#define CAP  512
#define BAND 1e-3f

// scratch (device globals; no allocation allowed)
__device__ __align__(16) __half g_w1h[DIM * HID];  // aW1 fp16, [k][n]
__device__ float    g_part[GCHUNKS * BATCH * DIM];
__device__ float    g_p1[KCHUNKS * BATCH * DIM];
__device__ float    g_p2[KCHUNKS * BATCH * DIM];
__device__ unsigned g_thr[BATCH];                 // approx kth weight (bits)
__device__ int      g_above[BATCH];               // #(w > thr+BAND)
__device__ int      g_ccnt[BATCH];                // candidate count
__device__ int      g_cand[BATCH][CAP];           // candidate indices
__device__ float    g_cval[BATCH][CAP];           // refined fp32 weights
__device__ unsigned char g_flag[BATCH * NINST];   // boundary-selected flags

__device__ __forceinline__ float gelu_f(float v) {
    float u = 0.7978845608028654f * (v + 0.044715f * v * v * v);
    return 0.5f * v * (1.0f + tanhf(u));
}

__device__ __forceinline__ void cp16(uint32_t sdst, const void* gsrc) {
    asm volatile("cp.async.cg.shared.global [%0], [%1], 16;" :: "r"(sdst), "l"(gsrc));
}

__device__ __forceinline__ void hmma(float* c, const unsigned* a, const unsigned* b) {
    asm volatile(
        "mma.sync.aligned.m16n8k16.row.col.f32.f16.f16.f32 "
        "{%0,%1,%2,%3}, {%4,%5,%6,%7}, {%8,%9}, {%0,%1,%2,%3};"
        : "+f"(c[0]), "+f"(c[1]), "+f"(c[2]), "+f"(c[3])
        : "r"(a[0]), "r"(a[1]), "r"(a[2]), "r"(a[3]), "r"(b[0]), "r"(b[1]));
}

__device__ __forceinline__ void ldm_x4t(unsigned* r, uint32_t addr) {
    asm volatile("ldmatrix.sync.aligned.m8n8.x4.trans.shared.b16 {%0,%1,%2,%3}, [%4];"
                 : "=r"(r[0]), "=r"(r[1]), "=r"(r[2]), "=r"(r[3]) : "r"(addr));
}

// ---------------------------------------------------------------------------
// Kernel 0: round aW1 to fp16.
// ---------------------------------------------------------------------------
__global__ __launch_bounds__(256) void conv_w1_kernel(const float* __restrict__ aW1)
{
    int i = blockIdx.x * 256 + threadIdx.x;
    if (i < DIM * HID)
        g_w1h[i] = __float2half_rn(aW1[i]);
}

// ---------------------------------------------------------------------------
// Kernel 1: fused attention-score MLP, fp16 HMMA.
// Warp layout 8M x 1N: warp tile 16 rows x 64 hid, acc[8][4].
// A fragments built DIRECTLY from gmem-loaded registers in mma layout
// (lane l: rows l>>2 and (l>>2)+8; k pairs 2(l&3)+{0,8} per k16 step) —
// no A smem, no A ldmatrix, no cross-warp epilogue reduction.
// B: smem double-buffered, ONE barrier per chunk (validated R13 ordering):
//   wait_group 0 -> barrier -> issue loadB(c+1) -> ldmatrix/MMA.
// ---------------------------------------------------------------------------
__global__ __launch_bounds__(256) void attn_kernel(
    const float* __restrict__ x,
    const float* __restrict__ ab1,
    const float* __restrict__ aW2,
    const float* __restrict__ ab2,
    float* __restrict__ wout)
{
    __shared__ __align__(16) __half Bh[2][BK][72];

    const int tid  = threadIdx.x;
    const int lane = tid & 31;
    const int warp = tid >> 5;          // 0..7 -> 16-row tile
    const int lr = lane >> 2;           // 0..7
    const int lk = lane & 3;            // 0..3
    const long rowBase = (long)blockIdx.x * BM;

    const float* xp0 = x + (rowBase + warp * 16 + lr) * DIM + 2 * lk;
    const float* xp1 = xp0 + 8 * DIM;   // row +8

    float acc[8][4];
    #pragma unroll
    for (int ni = 0; ni < 8; ni++)
        #pragma unroll
        for (int q = 0; q < 4; q++) acc[ni][q] = 0.f;

    auto loadB = [&](int s, int c) {
        int r = tid >> 3, g = tid & 7;
        uint32_t dh = (uint32_t)__cvta_generic_to_shared(&Bh[s][r][g * 8]);
        cp16(dh, g_w1h + (c * BK + r) * HID + g * 8);
        asm volatile("cp.async.commit_group;");
    };

    auto loadA = [&](float2* d, int c) {
        d[0] = *reinterpret_cast<const float2*>(xp0 + c * BK);
        d[1] = *reinterpret_cast<const float2*>(xp1 + c * BK);
        d[2] = *reinterpret_cast<const float2*>(xp0 + c * BK + 8);
        d[3] = *reinterpret_cast<const float2*>(xp1 + c * BK + 8);
        d[4] = *reinterpret_cast<const float2*>(xp0 + c * BK + 16);
        d[5] = *reinterpret_cast<const float2*>(xp1 + c * BK + 16);
        d[6] = *reinterpret_cast<const float2*>(xp0 + c * BK + 24);
        d[7] = *reinterpret_cast<const float2*>(xp1 + c * BK + 24);
    };

    loadB(0, 0);   // prologue: B group for chunk 0 in flight
    float2 af[8];
    loadA(af, 0);

    for (int c = 0; c < NCH; c++) {
        const int st = c & 1;
        float2 an[8];
        if (c + 1 < NCH) loadA(an, c + 1);

        // chunk c's B group completes; barrier publishes it + orders prior reads
        asm volatile("cp.async.wait_group 0;");
        __syncthreads();
        if (c + 1 < NCH)
            loadB((c + 1) & 1, c + 1);

        // convert A fragments (fp32 pairs -> half2), mma layout
        unsigned Af[8];
        #pragma unroll
        for (int e = 0; e < 8; e++) {
            __half2 hp = __float22half2_rn(make_float2(af[e].x, af[e].y));
            Af[e] = *reinterpret_cast<unsigned*>(&hp);
        }

        #pragma unroll
        for (int ks = 0; ks < 2; ks++) {
            unsigned Ahf[4] = {Af[ks * 4 + 0], Af[ks * 4 + 1],
                               Af[ks * 4 + 2], Af[ks * 4 + 3]};
            unsigned Bhf[8][2];
            #pragma unroll
            for (int pr = 0; pr < 4; pr++) {
                int brow = ks * 16 + (lane & 15);
                int bcol = pr * 16 + ((lane >> 4) << 3);
                unsigned t4[4];
                uint32_t bb = (uint32_t)__cvta_generic_to_shared(&Bh[st][brow][bcol]);
                ldm_x4t(t4, bb);
                Bhf[pr * 2][0] = t4[0]; Bhf[pr * 2][1] = t4[1];
                Bhf[pr * 2 + 1][0] = t4[2]; Bhf[pr * 2 + 1][1] = t4[3];
            }
            #pragma unroll
            for (int ni = 0; ni < 8; ni++)
                hmma(acc[ni], Ahf, Bhf[ni]);
        }
        #pragma unroll
        for (int e = 0; e < 8; e++) af[e] = an[e];
    }

    // epilogue: gelu(acc + b1) . w2, reduce over 4 lk-lanes, sigmoid.
    // acc[ni][0/1]: row lr,   cols ni*8+2lk, +1
    // acc[ni][2/3]: row lr+8, cols ni*8+2lk, +1
    float p0 = 0.f, p1 = 0.f;
    #pragma unroll
    for (int ni = 0; ni < 8; ni++) {
        int col = ni * 8 + 2 * lk;
        float b0 = ab1[col], b1c = ab1[col + 1];
        float w0 = aW2[col], w1c = aW2[col + 1];
        p0 += gelu_f(acc[ni][0] + b0) * w0 + gelu_f(acc[ni][1] + b1c) * w1c;
        p1 += gelu_f(acc[ni][2] + b0) * w0 + gelu_f(acc[ni][3] + b1c) * w1c;
    }
    p0 += __shfl_xor_sync(0xffffffffu, p0, 1);
    p0 += __shfl_xor_sync(0xffffffffu, p0, 2);
    p1 += __shfl_xor_sync(0xffffffffu, p1, 1);
    p1 += __shfl_xor_sync(0xffffffffu, p1, 2);
    if (lk == 0) {
        float bias2 = ab2[0];
        long r = rowBase + warp * 16 + lr;
        wout[r]     = 1.0f / (1.0f + expf(-(p0 + bias2)));
        wout[r + 8] = 1.0f / (1.0f + expf(-(p1 + bias2)));
    }
}

// ---------------------------------------------------------------------------
// Kernel 2: radix-select with parallel suffix-scan bucket pick.
// ---------------------------------------------------------------------------
__global__ __launch_bounds__(512) void select_kernel(const float* __restrict__ w)
{
    __shared__ unsigned sv[NINST];
    __shared__ int hist[16][256];
    __shared__ int scan[256];
    __shared__ unsigned s_prefix;
    __shared__ int s_k, s_above, s_cnt;

    const int b = blockIdx.x;
    const int tid = threadIdx.x;
    const int wid = tid >> 5;
    const float* wb = w + b * NINST;

    for (int i = tid; i < NINST; i += 512)
        sv[i] = __float_as_uint(wb[i]);
    if (tid == 0) { s_prefix = 0u; s_k = TOPK_K; s_above = 0; s_cnt = 0; }
    __syncthreads();

    for (int r = 0; r < 4; r++) {
        for (int i = tid; i < 16 * 256; i += 512)
            hist[i >> 8][i & 255] = 0;
        __syncthreads();
        const unsigned pref = s_prefix;
        const int k = s_k;
        const int sh = 24 - 8 * r;
        for (int i = tid; i < NINST; i += 512) {
            unsigned v = sv[i];
            bool ok = (r == 0) || ((v >> (sh + 8)) == pref);
            if (ok) atomicAdd(&hist[wid][(v >> sh) & 255], 1);
        }
        __syncthreads();
        if (tid < 256) {
            int s = hist[0][tid];
            #pragma unroll
            for (int h = 1; h < 16; h++) s += hist[h][tid];
            scan[tid] = s;
        }
        __syncthreads();
        #pragma unroll
        for (int off = 1; off < 256; off <<= 1) {
            int add = 0;
            if (tid < 256 && tid + off < 256) add = scan[tid + off];
            __syncthreads();
            if (tid < 256) scan[tid] += add;
            __syncthreads();
        }
        if (tid < 256) {
            int cumi  = scan[tid];
            int cumnx = (tid == 255) ? 0 : scan[tid + 1];
            if (cumi >= k && cumnx < k) {
                s_prefix = (pref << 8) | (unsigned)tid;
                s_k = k - cumnx;
            }
        }
        __syncthreads();
    }

    const float t   = __uint_as_float(s_prefix);
    const float thi = t + BAND;
    const float tlo = t - BAND;

    int la = 0;
    for (int i = tid; i < NINST; i += 512) {
        float wv = __uint_as_float(sv[i]);
        g_flag[b * NINST + i] = 0;
        if (wv > thi) la++;
        else if (wv >= tlo) {
            int p = atomicAdd(&s_cnt, 1);
            if (p < CAP) g_cand[b][p] = i;
        }
    }
    atomicAdd(&s_above, la);
    __syncthreads();
    if (tid == 0) {
        g_thr[b]   = s_prefix;
        g_above[b] = s_above;
        g_ccnt[b]  = s_cnt < CAP ? s_cnt : CAP;
    }
}

// ---------------------------------------------------------------------------
// Kernel 3: exact fp32 score recompute for band candidates (R13 config).
// ---------------------------------------------------------------------------
__global__ __launch_bounds__(256) void refine_kernel(
    const float* __restrict__ x,  const float* __restrict__ aW1,
    const float* __restrict__ ab1, const float* __restrict__ aW2,
    const float* __restrict__ ab2)
{
    const int b = blockIdx.y;
    const int cnt = g_ccnt[b];
    __shared__ float sx[DIM];
    __shared__ float sh4[4][64];
    __shared__ float sr[2];
    const int tid = threadIdx.x;
    const int q = tid >> 6;
    const int j = tid & 63;

    for (int ci = blockIdx.x; ci < cnt; ci += 64) {
        const int idx = g_cand[b][ci];
        const float* xr = x + ((long)b * NINST + idx) * DIM;
        sx[tid]       = xr[tid];
        sx[tid + 256] = xr[tid + 256];
        __syncthreads();

        const float* wp = aW1 + (long)(q * 128) * HID + j;
        const float* xq = sx + q * 128;
        float acc = 0.f;
        #pragma unroll
        for (int g0 = 0; g0 < 128; g0 += 16) {
            float wv[16];
            #pragma unroll
            for (int t = 0; t < 16; t++)
                wv[t] = wp[(long)(g0 + t) * HID];
            #pragma unroll
            for (int t = 0; t < 16; t++)
                acc += xq[g0 + t] * wv[t];
        }
        sh4[q][j] = acc;
        __syncthreads();

        if (tid < 64) {
            float hsum = sh4[0][j] + sh4[1][j] + sh4[2][j] + sh4[3][j];
            float hv = gelu_f(hsum + ab1[j]) * aW2[j];
            #pragma unroll
            for (int off = 16; off >= 1; off >>= 1)
                hv += __shfl_down_sync(0xffffffffu, hv, off);
            if ((j & 31) == 0) sr[j >> 5] = hv;
        }
        __syncthreads();
        if (tid == 0) {
            float logit = sr[0] + sr[1] + ab2[0];
            g_cval[b][ci] = 1.0f / (1.0f + expf(-logit));
        }
        __syncthreads();
    }
}

// ---------------------------------------------------------------------------
// Kernel 4: exact ranking among candidates -> flags (value desc, index asc).
// ---------------------------------------------------------------------------
__global__ __launch_bounds__(256) void finalize_kernel()
{
    __shared__ float v[CAP];
    __shared__ int  ix[CAP];
    const int b = blockIdx.x;
    const int tid = threadIdx.x;
    const int cnt  = g_ccnt[b];
    const int need = TOPK_K - g_above[b];

    for (int i = tid; i < cnt; i += 256) { v[i] = g_cval[b][i]; ix[i] = g_cand[b][i]; }
    __syncthreads();
    for (int i = tid; i < cnt; i += 256) {
        float vi = v[i]; int xi = ix[i];
        int rank = 0;
        for (int j = 0; j < cnt; j++)
            rank += (v[j] > vi) || (v[j] == vi && ix[j] < xi);
        if (rank < need) g_flag[b * NINST + xi] = 1;
    }
}

// ---------------------------------------------------------------------------
// Kernel 5: weighted gather-sum with per-block index compaction.
// ---------------------------------------------------------------------------
__global__ __launch_bounds__(128) void gather_kernel(
    const float* __restrict__ x, const float* __restrict__ w)
{
    __shared__ int   sel[GROWS];
    __shared__ float sw[GROWS];
    __shared__ int   wbase[4];
    __shared__ int   scount;

    const int b  = blockIdx.y;
    const int rc = blockIdx.x;
    const int r0 = rc * GROWS;
    const int tid = threadIdx.x;
    const int lane = tid & 31;
    const int wrp = tid >> 5;

    const float thi = __uint_as_float(g_thr[b]) + BAND;

    float wi = w[b * NINST + r0 + tid];
    bool pick = (wi > thi) || g_flag[b * NINST + r0 + tid];
    unsigned mask = __ballot_sync(0xffffffffu, pick);
    int wcnt = __popc(mask);
    if (lane == 0) wbase[wrp] = wcnt;
    __syncthreads();
    if (tid == 0) {
        int s = 0;
        #pragma unroll
        for (int q = 0; q < 4; q++) { int c = wbase[q]; wbase[q] = s; s += c; }
        scount = s;
    }
    __syncthreads();
    if (pick) {
        int pos = wbase[wrp] + __popc(mask & ((1u << lane) - 1u));
        sel[pos] = tid;
        sw[pos]  = wi;
    }
    __syncthreads();

    const int d4 = tid * 4;
    const int nsel = scount;
    const float* xb = x + ((long)b * NINST + r0) * DIM + d4;

    float4 acc = make_float4(0.f, 0.f, 0.f, 0.f);
    for (int s = 0; s < nsel; s++) {
        float ws = sw[s];
        float4 xv = *reinterpret_cast<const float4*>(xb + (long)sel[s] * DIM);
        acc.x += ws * xv.x; acc.y += ws * xv.y;
        acc.z += ws * xv.z; acc.w += ws * xv.w;
    }
    *reinterpret_cast<float4*>(&g_part[(rc * BATCH + b) * DIM + d4]) = acc;
}

// ---------------------------------------------------------------------------
// Kernel 6: mlp1 split-K partials with inline emb reduction.
// ---------------------------------------------------------------------------
__global__ __launch_bounds__(128) void mlp1_part_kernel(
    const float* __restrict__ W, float* __restrict__ part)
{
    __shared__ float s_in[BATCH][KLEN];
    const int kc = blockIdx.y;
    const int j  = blockIdx.x * 128 + threadIdx.x;

    #pragma unroll
    for (int it = 0; it < (BATCH * KLEN) / 128; it++) {
        int i = it * 128 + threadIdx.x;
        int bb = i / KLEN, dd = i % KLEN;
        const float* p = g_part + bb * DIM + kc * KLEN + dd;
        float s0 = 0.f, s1 = 0.f;
        #pragma unroll
        for (int rc = 0; rc < GCHUNKS; rc += 2) {
            s0 += p[(long)rc * BATCH * DIM];
            s1 += p[(long)(rc + 1) * BATCH * DIM];
        }
        s_in[bb][dd] = (s0 + s1) * (1.0f / (float)TOPK_K);
    }
    __syncthreads();

    float acc[BATCH];
    #pragma unroll
    for (int bb = 0; bb < BATCH; bb++) acc[bb] = 0.f;

    #pragma unroll 4
    for (int dd = 0; dd < KLEN; dd++) {
        float wv = W[(long)(kc * KLEN + dd) * DIM + j];
        #pragma unroll
        for (int bb = 0; bb < BATCH; bb++)
            acc[bb] += s_in[bb][dd] * wv;
    }
    #pragma unroll
    for (int bb = 0; bb < BATCH; bb++)
        part[(kc * BATCH + bb) * DIM + j] = acc[bb];
}

// ---------------------------------------------------------------------------
// Kernel 7: mlp2 split-K partials with inline (reduce p1 + bias + gelu).
// ---------------------------------------------------------------------------
__global__ __launch_bounds__(128) void mlp2_part_kernel(
    const float* __restrict__ W, const float* __restrict__ b1,
    float* __restrict__ part)
{
    __shared__ float s_in[BATCH][KLEN];
    const int kc = blockIdx.y;
    const int j  = blockIdx.x * 128 + threadIdx.x;

    #pragma unroll
    for (int it = 0; it < (BATCH * KLEN) / 128; it++) {
        int i = it * 128 + threadIdx.x;
        int bb = i / KLEN, dd = i % KLEN;
        const float* p = g_p1 + bb * DIM + kc * KLEN + dd;
        float s = 0.f;
        #pragma unroll
        for (int c = 0; c < KCHUNKS; c++)
            s += p[(long)c * BATCH * DIM];
        s_in[bb][dd] = gelu_f(s + b1[kc * KLEN + dd]);
    }
    __syncthreads();

    float acc[BATCH];
    #pragma unroll
    for (int bb = 0; bb < BATCH; bb++) acc[bb] = 0.f;

    #pragma unroll 4
    for (int dd = 0; dd < KLEN; dd++) {
        float wv = W[(long)(kc * KLEN + dd) * DIM + j];
        #pragma unroll
        for (int bb = 0; bb < BATCH; bb++)
            acc[bb] += s_in[bb][dd] * wv;
    }
    #pragma unroll
    for (int bb = 0; bb < BATCH; bb++)
        part[(kc * BATCH + bb) * DIM + j] = acc[bb];
}

// ---------------------------------------------------------------------------
// Kernel 8: reduce mlp2 partials + bias -> out.
// ---------------------------------------------------------------------------
__global__ __launch_bounds__(512) void mlp2_reduce_kernel(
    const float* __restrict__ bias, float* __restrict__ out)
{
    const int b = blockIdx.x;
    const int j = threadIdx.x;
    float s = 0.f;
    #pragma unroll
    for (int kc = 0; kc < KCHUNKS; kc++)
        s += g_p2[(kc * BATCH + b) * DIM + j];
    out[b * DIM + j] = s + bias[j];
}

// ---------------------------------------------------------------------------
extern "C" void kernel_launch(void* const* d_in, const int* in_sizes, int n_in,
                              void* d_out, int out_size)
{
    const float* x   = (const float*)d_in[0];
    const float* aW1 = (const float*)d_in[1];
    const float* ab1 = (const float*)d_in[2];
    const float* aW2 = (const float*)d_in[3];
    const float* ab2 = (const float*)d_in[4];
    const float* pW1 = (const float*)d_in[5];
    const float* pb1 = (const float*)d_in[6];
    const float* pW2 = (const float*)d_in[7];
    const float* pb2 = (const float*)d_in[8];

    float* out = (float*)d_out;
    float* proj    = out;                 // [B, DIM]
    float* weights = out + BATCH * DIM;   // [B, NINST]

    float* d_p1;  cudaGetSymbolAddress((void**)&d_p1, g_p1);
    float* d_p2;  cudaGetSymbolAddress((void**)&d_p2, g_p2);

    conv_w1_kernel<<<(DIM * HID + 255) / 256, 256>>>(aW1);
    attn_kernel<<<(BATCH * NINST) / BM, 256>>>(x, ab1, aW2, ab2, weights);
    select_kernel<<<BATCH, 512>>>(weights);
    refine_kernel<<<dim3(64, BATCH), 256>>>(x, aW1, ab1, aW2, ab2);
    finalize_kernel<<<BATCH, 256>>>();
    gather_kernel<<<dim3(GCHUNKS, BATCH), 128>>>(x, weights);
    mlp1_part_kernel<<<dim3(DIM / 128, KCHUNKS), 128>>>(pW1, d_p1);
    mlp2_part_kernel<<<dim3(DIM / 128, KCHUNKS), 128>>>(pW2, pb1, d_p2);
    mlp2_reduce_kernel<<<BATCH, 512>>>(pb2, proj);
}

// round 17
// speedup vs baseline: 1.0862x; 1.0382x over previous
#include <cuda_runtime.h>
#include <cuda_fp16.h>
#include <math.h>
#include <stdint.h>

#define BATCH 8
#define NINST 8192
#define DIM   512
#define HID   64
#define TOPK_K 2457

#define GCHUNKS 64
#define GROWS   (NINST / GCHUNKS)   // 128

#define KCHUNKS 16
#define KLEN    (DIM / KCHUNKS)     // 32

// attn tiling
#define BM 128
#define BN 64
#define BK 32
#define NCH (DIM / BK)              // 16

#define CAP  512
#define BAND 1e-3f

// scratch (device globals; no allocation allowed)
__device__ __align__(16) __half g_w1h[DIM * HID];  // aW1 fp16, [k][n]
__device__ float    g_part[GCHUNKS * BATCH * DIM];
__device__ float    g_p1[KCHUNKS * BATCH * DIM];
__device__ float    g_p2[KCHUNKS * BATCH * DIM];
__device__ unsigned g_thr[BATCH];                 // approx kth weight (bits)
__device__ int      g_above[BATCH];               // #(w > thr+BAND)
__device__ int      g_ccnt[BATCH];                // candidate count
__device__ int      g_cand[BATCH][CAP];           // candidate indices
__device__ float    g_cval[BATCH][CAP];           // refined fp32 weights
__device__ unsigned char g_flag[BATCH * NINST];   // boundary-selected flags

__device__ __forceinline__ float gelu_f(float v) {
    float u = 0.7978845608028654f * (v + 0.044715f * v * v * v);
    return 0.5f * v * (1.0f + tanhf(u));
}

__device__ __forceinline__ void cp16(uint32_t sdst, const void* gsrc) {
    asm volatile("cp.async.cg.shared.global [%0], [%1], 16;" :: "r"(sdst), "l"(gsrc));
}

__device__ __forceinline__ void hmma(float* c, const unsigned* a, const unsigned* b) {
    asm volatile(
        "mma.sync.aligned.m16n8k16.row.col.f32.f16.f16.f32 "
        "{%0,%1,%2,%3}, {%4,%5,%6,%7}, {%8,%9}, {%0,%1,%2,%3};"
        : "+f"(c[0]), "+f"(c[1]), "+f"(c[2]), "+f"(c[3])
        : "r"(a[0]), "r"(a[1]), "r"(a[2]), "r"(a[3]), "r"(b[0]), "r"(b[1]));
}

__device__ __forceinline__ void ldm_x4t(unsigned* r, uint32_t addr) {
    asm volatile("ldmatrix.sync.aligned.m8n8.x4.trans.shared.b16 {%0,%1,%2,%3}, [%4];"
                 : "=r"(r[0]), "=r"(r[1]), "=r"(r[2]), "=r"(r[3]) : "r"(addr));
}

// ---------------------------------------------------------------------------
// Kernel 0: round aW1 to fp16.
// ---------------------------------------------------------------------------
__global__ __launch_bounds__(256) void conv_w1_kernel(const float* __restrict__ aW1)
{
    int i = blockIdx.x * 256 + threadIdx.x;
    if (i < DIM * HID)
        g_w1h[i] = __float2half_rn(aW1[i]);
}

// ---------------------------------------------------------------------------
// Kernel 1: fused attention-score MLP, fp16 HMMA, direct-A from gmem with a
// k-permutation so each lane loads ONE contiguous float4 per (row, k16-group):
//   lane lk loads k = 4lk..4lk+3; fragment slots want k = {2lk,2lk+1,2lk+8,
//   2lk+9}. Permutation pi(4lk+j) = 2lk + (j&1) + (j>=2 ? 8 : 0) applied to
//   B's smem row placement keeps A-slot k == B-row k. Halves LDG issue count
//   vs float2 layout (4x LDG.128 per thread per chunk).
// B: smem double-buffered, ONE barrier per chunk (validated R13 ordering).
// ---------------------------------------------------------------------------
__global__ __launch_bounds__(256) void attn_kernel(
    const float* __restrict__ x,
    const float* __restrict__ ab1,
    const float* __restrict__ aW2,
    const float* __restrict__ ab2,
    float* __restrict__ wout)
{
    __shared__ __align__(16) __half Bh[2][BK][72];

    const int tid  = threadIdx.x;
    const int lane = tid & 31;
    const int warp = tid >> 5;          // 0..7 -> 16-row tile
    const int lr = lane >> 2;           // 0..7
    const int lk = lane & 3;            // 0..3
    const long rowBase = (long)blockIdx.x * BM;

    // contiguous float4 base: row, k-offset 4*lk
    const float* xq0 = x + (rowBase + warp * 16 + lr) * DIM + 4 * lk;
    const float* xq1 = xq0 + 8 * DIM;   // row +8

    float acc[8][4];
    #pragma unroll
    for (int ni = 0; ni < 8; ni++)
        #pragma unroll
        for (int q = 0; q < 4; q++) acc[ni][q] = 0.f;

    // B loader with k-permutation within each 16-row group.
    auto loadB = [&](int s, int c) {
        int r = tid >> 3, g = tid & 7;       // r: 0..31 gmem k-row, g: 16B col
        int o = r & 15;
        int lkk = o >> 2, j = o & 3;
        int p = (r & 16) + 2 * lkk + (j & 1) + ((j & 2) ? 8 : 0);
        uint32_t dh = (uint32_t)__cvta_generic_to_shared(&Bh[s][p][g * 8]);
        cp16(dh, g_w1h + (c * BK + r) * HID + g * 8);
        asm volatile("cp.async.commit_group;");
    };

    auto loadA = [&](float4* d, int c) {
        d[0] = *reinterpret_cast<const float4*>(xq0 + c * BK);        // row lr,  g0
        d[1] = *reinterpret_cast<const float4*>(xq1 + c * BK);        // row lr+8,g0
        d[2] = *reinterpret_cast<const float4*>(xq0 + c * BK + 16);   // row lr,  g1
        d[3] = *reinterpret_cast<const float4*>(xq1 + c * BK + 16);   // row lr+8,g1
    };

    loadB(0, 0);   // prologue: B group for chunk 0 in flight
    float4 af[4];
    loadA(af, 0);

    for (int c = 0; c < NCH; c++) {
        const int st = c & 1;
        float4 an[4];
        if (c + 1 < NCH) loadA(an, c + 1);

        // chunk c's B group completes; barrier publishes it + orders prior reads
        asm volatile("cp.async.wait_group 0;");
        __syncthreads();
        if (c + 1 < NCH)
            loadB((c + 1) & 1, c + 1);

        // build A fragments: slot pairs (x,y) -> permuted k 2lk,2lk+1;
        // (z,w) -> permuted k 2lk+8,2lk+9
        unsigned Af[2][4];
        #pragma unroll
        for (int g = 0; g < 2; g++) {
            __half2 h0 = __float22half2_rn(make_float2(af[2 * g].x,     af[2 * g].y));
            __half2 h1 = __float22half2_rn(make_float2(af[2 * g + 1].x, af[2 * g + 1].y));
            __half2 h2v = __float22half2_rn(make_float2(af[2 * g].z,     af[2 * g].w));
            __half2 h3 = __float22half2_rn(make_float2(af[2 * g + 1].z, af[2 * g + 1].w));
            Af[g][0] = *reinterpret_cast<unsigned*>(&h0);
            Af[g][1] = *reinterpret_cast<unsigned*>(&h1);
            Af[g][2] = *reinterpret_cast<unsigned*>(&h2v);
            Af[g][3] = *reinterpret_cast<unsigned*>(&h3);
        }

        #pragma unroll
        for (int ks = 0; ks < 2; ks++) {
            unsigned Bhf[8][2];
            #pragma unroll
            for (int pr = 0; pr < 4; pr++) {
                int brow = ks * 16 + (lane & 15);
                int bcol = pr * 16 + ((lane >> 4) << 3);
                unsigned t4[4];
                uint32_t bb = (uint32_t)__cvta_generic_to_shared(&Bh[st][brow][bcol]);
                ldm_x4t(t4, bb);
                Bhf[pr * 2][0] = t4[0]; Bhf[pr * 2][1] = t4[1];
                Bhf[pr * 2 + 1][0] = t4[2]; Bhf[pr * 2 + 1][1] = t4[3];
            }
            #pragma unroll
            for (int ni = 0; ni < 8; ni++)
                hmma(acc[ni], Af[ks], Bhf[ni]);
        }
        #pragma unroll
        for (int e = 0; e < 4; e++) af[e] = an[e];
    }

    // epilogue: gelu(acc + b1) . w2, reduce over 4 lk-lanes, sigmoid.
    float p0 = 0.f, p1 = 0.f;
    #pragma unroll
    for (int ni = 0; ni < 8; ni++) {
        int col = ni * 8 + 2 * lk;
        float b0 = ab1[col], b1c = ab1[col + 1];
        float w0 = aW2[col], w1c = aW2[col + 1];
        p0 += gelu_f(acc[ni][0] + b0) * w0 + gelu_f(acc[ni][1] + b1c) * w1c;
        p1 += gelu_f(acc[ni][2] + b0) * w0 + gelu_f(acc[ni][3] + b1c) * w1c;
    }
    p0 += __shfl_xor_sync(0xffffffffu, p0, 1);
    p0 += __shfl_xor_sync(0xffffffffu, p0, 2);
    p1 += __shfl_xor_sync(0xffffffffu, p1, 1);
    p1 += __shfl_xor_sync(0xffffffffu, p1, 2);
    if (lk == 0) {
        float bias2 = ab2[0];
        long r = rowBase + warp * 16 + lr;
        wout[r]     = 1.0f / (1.0f + expf(-(p0 + bias2)));
        wout[r + 8] = 1.0f / (1.0f + expf(-(p1 + bias2)));
    }
}

// ---------------------------------------------------------------------------
// Kernel 2: radix-select with parallel suffix-scan bucket pick.
// ---------------------------------------------------------------------------
__global__ __launch_bounds__(512) void select_kernel(const float* __restrict__ w)
{
    __shared__ unsigned sv[NINST];
    __shared__ int hist[16][256];
    __shared__ int scan[256];
    __shared__ unsigned s_prefix;
    __shared__ int s_k, s_above, s_cnt;

    const int b = blockIdx.x;
    const int tid = threadIdx.x;
    const int wid = tid >> 5;
    const float* wb = w + b * NINST;

    for (int i = tid; i < NINST; i += 512)
        sv[i] = __float_as_uint(wb[i]);
    if (tid == 0) { s_prefix = 0u; s_k = TOPK_K; s_above = 0; s_cnt = 0; }
    __syncthreads();

    for (int r = 0; r < 4; r++) {
        for (int i = tid; i < 16 * 256; i += 512)
            hist[i >> 8][i & 255] = 0;
        __syncthreads();
        const unsigned pref = s_prefix;
        const int k = s_k;
        const int sh = 24 - 8 * r;
        for (int i = tid; i < NINST; i += 512) {
            unsigned v = sv[i];
            bool ok = (r == 0) || ((v >> (sh + 8)) == pref);
            if (ok) atomicAdd(&hist[wid][(v >> sh) & 255], 1);
        }
        __syncthreads();
        if (tid < 256) {
            int s = hist[0][tid];
            #pragma unroll
            for (int h = 1; h < 16; h++) s += hist[h][tid];
            scan[tid] = s;
        }
        __syncthreads();
        #pragma unroll
        for (int off = 1; off < 256; off <<= 1) {
            int add = 0;
            if (tid < 256 && tid + off < 256) add = scan[tid + off];
            __syncthreads();
            if (tid < 256) scan[tid] += add;
            __syncthreads();
        }
        if (tid < 256) {
            int cumi  = scan[tid];
            int cumnx = (tid == 255) ? 0 : scan[tid + 1];
            if (cumi >= k && cumnx < k) {
                s_prefix = (pref << 8) | (unsigned)tid;
                s_k = k - cumnx;
            }
        }
        __syncthreads();
    }

    const float t   = __uint_as_float(s_prefix);
    const float thi = t + BAND;
    const float tlo = t - BAND;

    int la = 0;
    for (int i = tid; i < NINST; i += 512) {
        float wv = __uint_as_float(sv[i]);
        g_flag[b * NINST + i] = 0;
        if (wv > thi) la++;
        else if (wv >= tlo) {
            int p = atomicAdd(&s_cnt, 1);
            if (p < CAP) g_cand[b][p] = i;
        }
    }
    atomicAdd(&s_above, la);
    __syncthreads();
    if (tid == 0) {
        g_thr[b]   = s_prefix;
        g_above[b] = s_above;
        g_ccnt[b]  = s_cnt < CAP ? s_cnt : CAP;
    }
}

// ---------------------------------------------------------------------------
// Kernel 3: exact fp32 score recompute for band candidates.
// ---------------------------------------------------------------------------
__global__ __launch_bounds__(256) void refine_kernel(
    const float* __restrict__ x,  const float* __restrict__ aW1,
    const float* __restrict__ ab1, const float* __restrict__ aW2,
    const float* __restrict__ ab2)
{
    const int b = blockIdx.y;
    const int cnt = g_ccnt[b];
    __shared__ float sx[DIM];
    __shared__ float sh4[4][64];
    __shared__ float sr[2];
    const int tid = threadIdx.x;
    const int q = tid >> 6;
    const int j = tid & 63;

    for (int ci = blockIdx.x; ci < cnt; ci += 64) {
        const int idx = g_cand[b][ci];
        const float* xr = x + ((long)b * NINST + idx) * DIM;
        sx[tid]       = xr[tid];
        sx[tid + 256] = xr[tid + 256];
        __syncthreads();

        const float* wp = aW1 + (long)(q * 128) * HID + j;
        const float* xq = sx + q * 128;
        float acc = 0.f;
        #pragma unroll
        for (int g0 = 0; g0 < 128; g0 += 16) {
            float wv[16];
            #pragma unroll
            for (int t = 0; t < 16; t++)
                wv[t] = wp[(long)(g0 + t) * HID];
            #pragma unroll
            for (int t = 0; t < 16; t++)
                acc += xq[g0 + t] * wv[t];
        }
        sh4[q][j] = acc;
        __syncthreads();

        if (tid < 64) {
            float hsum = sh4[0][j] + sh4[1][j] + sh4[2][j] + sh4[3][j];
            float hv = gelu_f(hsum + ab1[j]) * aW2[j];
            #pragma unroll
            for (int off = 16; off >= 1; off >>= 1)
                hv += __shfl_down_sync(0xffffffffu, hv, off);
            if ((j & 31) == 0) sr[j >> 5] = hv;
        }
        __syncthreads();
        if (tid == 0) {
            float logit = sr[0] + sr[1] + ab2[0];
            g_cval[b][ci] = 1.0f / (1.0f + expf(-logit));
        }
        __syncthreads();
    }
}

// ---------------------------------------------------------------------------
// Kernel 4: exact ranking among candidates -> flags (value desc, index asc).
// ---------------------------------------------------------------------------
__global__ __launch_bounds__(256) void finalize_kernel()
{
    __shared__ float v[CAP];
    __shared__ int  ix[CAP];
    const int b = blockIdx.x;
    const int tid = threadIdx.x;
    const int cnt  = g_ccnt[b];
    const int need = TOPK_K - g_above[b];

    for (int i = tid; i < cnt; i += 256) { v[i] = g_cval[b][i]; ix[i] = g_cand[b][i]; }
    __syncthreads();
    for (int i = tid; i < cnt; i += 256) {
        float vi = v[i]; int xi = ix[i];
        int rank = 0;
        for (int j = 0; j < cnt; j++)
            rank += (v[j] > vi) || (v[j] == vi && ix[j] < xi);
        if (rank < need) g_flag[b * NINST + xi] = 1;
    }
}

// ---------------------------------------------------------------------------
// Kernel 5: weighted gather-sum with per-block index compaction.
// ---------------------------------------------------------------------------
__global__ __launch_bounds__(128) void gather_kernel(
    const float* __restrict__ x, const float* __restrict__ w)
{
    __shared__ int   sel[GROWS];
    __shared__ float sw[GROWS];
    __shared__ int   wbase[4];
    __shared__ int   scount;

    const int b  = blockIdx.y;
    const int rc = blockIdx.x;
    const int r0 = rc * GROWS;
    const int tid = threadIdx.x;
    const int lane = tid & 31;
    const int wrp = tid >> 5;

    const float thi = __uint_as_float(g_thr[b]) + BAND;

    float wi = w[b * NINST + r0 + tid];
    bool pick = (wi > thi) || g_flag[b * NINST + r0 + tid];
    unsigned mask = __ballot_sync(0xffffffffu, pick);
    int wcnt = __popc(mask);
    if (lane == 0) wbase[wrp] = wcnt;
    __syncthreads();
    if (tid == 0) {
        int s = 0;
        #pragma unroll
        for (int q = 0; q < 4; q++) { int c = wbase[q]; wbase[q] = s; s += c; }
        scount = s;
    }
    __syncthreads();
    if (pick) {
        int pos = wbase[wrp] + __popc(mask & ((1u << lane) - 1u));
        sel[pos] = tid;
        sw[pos]  = wi;
    }
    __syncthreads();

    const int d4 = tid * 4;
    const int nsel = scount;
    const float* xb = x + ((long)b * NINST + r0) * DIM + d4;

    float4 acc = make_float4(0.f, 0.f, 0.f, 0.f);
    for (int s = 0; s < nsel; s++) {
        float ws = sw[s];
        float4 xv = *reinterpret_cast<const float4*>(xb + (long)sel[s] * DIM);
        acc.x += ws * xv.x; acc.y += ws * xv.y;
        acc.z += ws * xv.z; acc.w += ws * xv.w;
    }
    *reinterpret_cast<float4*>(&g_part[(rc * BATCH + b) * DIM + d4]) = acc;
}

// ---------------------------------------------------------------------------
// Kernel 6: mlp1 split-K partials with inline emb reduction.
// ---------------------------------------------------------------------------
__global__ __launch_bounds__(128) void mlp1_part_kernel(
    const float* __restrict__ W, float* __restrict__ part)
{
    __shared__ float s_in[BATCH][KLEN];
    const int kc = blockIdx.y;
    const int j  = blockIdx.x * 128 + threadIdx.x;

    #pragma unroll
    for (int it = 0; it < (BATCH * KLEN) / 128; it++) {
        int i = it * 128 + threadIdx.x;
        int bb = i / KLEN, dd = i % KLEN;
        const float* p = g_part + bb * DIM + kc * KLEN + dd;
        float s0 = 0.f, s1 = 0.f;
        #pragma unroll
        for (int rc = 0; rc < GCHUNKS; rc += 2) {
            s0 += p[(long)rc * BATCH * DIM];
            s1 += p[(long)(rc + 1) * BATCH * DIM];
        }
        s_in[bb][dd] = (s0 + s1) * (1.0f / (float)TOPK_K);
    }
    __syncthreads();

    float acc[BATCH];
    #pragma unroll
    for (int bb = 0; bb < BATCH; bb++) acc[bb] = 0.f;

    #pragma unroll 4
    for (int dd = 0; dd < KLEN; dd++) {
        float wv = W[(long)(kc * KLEN + dd) * DIM + j];
        #pragma unroll
        for (int bb = 0; bb < BATCH; bb++)
            acc[bb] += s_in[bb][dd] * wv;
    }
    #pragma unroll
    for (int bb = 0; bb < BATCH; bb++)
        part[(kc * BATCH + bb) * DIM + j] = acc[bb];
}

// ---------------------------------------------------------------------------
// Kernel 7: mlp2 split-K partials with inline (reduce p1 + bias + gelu).
// ---------------------------------------------------------------------------
__global__ __launch_bounds__(128) void mlp2_part_kernel(
    const float* __restrict__ W, const float* __restrict__ b1,
    float* __restrict__ part)
{
    __shared__ float s_in[BATCH][KLEN];
    const int kc = blockIdx.y;
    const int j  = blockIdx.x * 128 + threadIdx.x;

    #pragma unroll
    for (int it = 0; it < (BATCH * KLEN) / 128; it++) {
        int i = it * 128 + threadIdx.x;
        int bb = i / KLEN, dd = i % KLEN;
        const float* p = g_p1 + bb * DIM + kc * KLEN + dd;
        float s = 0.f;
        #pragma unroll
        for (int c = 0; c < KCHUNKS; c++)
            s += p[(long)c * BATCH * DIM];
        s_in[bb][dd] = gelu_f(s + b1[kc * KLEN + dd]);
    }
    __syncthreads();

    float acc[BATCH];
    #pragma unroll
    for (int bb = 0; bb < BATCH; bb++) acc[bb] = 0.f;

    #pragma unroll 4
    for (int dd = 0; dd < KLEN; dd++) {
        float wv = W[(long)(kc * KLEN + dd) * DIM + j];
        #pragma unroll
        for (int bb = 0; bb < BATCH; bb++)
            acc[bb] += s_in[bb][dd] * wv;
    }
    #pragma unroll
    for (int bb = 0; bb < BATCH; bb++)
        part[(kc * BATCH + bb) * DIM + j] = acc[bb];
}

// ---------------------------------------------------------------------------
// Kernel 8: reduce mlp2 partials + bias -> out.
// ---------------------------------------------------------------------------
__global__ __launch_bounds__(512) void mlp2_reduce_kernel(
    const float* __restrict__ bias, float* __restrict__ out)
{
    const int b = blockIdx.x;
    const int j = threadIdx.x;
    float s = 0.f;
    #pragma unroll
    for (int kc = 0; kc < KCHUNKS; kc++)
        s += g_p2[(kc * BATCH + b) * DIM + j];
    out[b * DIM + j] = s + bias[j];
}

// ---------------------------------------------------------------------------
extern "C" void kernel_launch(void* const* d_in, const int* in_sizes, int n_in,
                              void* d_out, int out_size)
{
    const float* x   = (const float*)d_in[0];
    const float* aW1 = (const float*)d_in[1];
    const float* ab1 = (const float*)d_in[2];
    const float* aW2 = (const float*)d_in[3];
    const float* ab2 = (const float*)d_in[4];
    const float* pW1 = (const float*)d_in[5];
    const float* pb1 = (const float*)d_in[6];
    const float* pW2 = (const float*)d_in[7];
    const float* pb2 = (const float*)d_in[8];

    float* out = (float*)d_out;
    float* proj    = out;                 // [B, DIM]
    float* weights = out + BATCH * DIM;   // [B, NINST]

    float* d_p1;  cudaGetSymbolAddress((void**)&d_p1, g_p1);
    float* d_p2;  cudaGetSymbolAddress((void**)&d_p2, g_p2);

    conv_w1_kernel<<<(DIM * HID + 255) / 256, 256>>>(aW1);
    attn_kernel<<<(BATCH * NINST) / BM, 256>>>(x, ab1, aW2, ab2, weights);
    select_kernel<<<BATCH, 512>>>(weights);
    refine_kernel<<<dim3(64, BATCH), 256>>>(x, aW1, ab1, aW2, ab2);
    finalize_kernel<<<BATCH, 256>>>();
    gather_kernel<<<dim3(GCHUNKS, BATCH), 128>>>(x, weights);
    mlp1_part_kernel<<<dim3(DIM / 128, KCHUNKS), 128>>>(pW1, d_p1);
    mlp2_part_kernel<<<dim3(DIM / 128, KCHUNKS), 128>>>(pW2, pb1, d_p2);
    mlp2_reduce_kernel<<<BATCH, 512>>>(pb2, proj);
}